// round 2
// baseline (speedup 1.0000x reference)
#include <cuda_runtime.h>
#include <math.h>

#define BATCH 8
#define CIN   128
#define CD    64
#define Hh    128
#define Ww    128
#define HW    (Hh*Ww)
#define NE    4

// ---- scratch (device globals; no allocation allowed) ----
__device__ float g_y[(size_t)BATCH*CD*HW];      // pre_fuse output, 33.5 MB
__device__ float g_pooled[BATCH*CD];            // max + mean pooled
__device__ float g_cof[BATCH*NE];               // gating coefficients (0 for unselected)

// ============================================================
// Kernel A: pre_fuse 1x1 conv  y[b,o,p] = sum_c x[b,c,p]*W[o,c] + bias[o]
// Block: 256 threads, computes all 64 output channels for 128 pixels.
// Register tile: 8 o x 4 p per thread.
// ============================================================
#define TP 128
__global__ void prefuse_kernel(const float* __restrict__ x,
                               const float* __restrict__ pre_w,
                               const float* __restrict__ pre_b) {
    __shared__ float w_s[CIN*CD];   // transposed: [c][o], 32 KB
    __shared__ float x_s[32*TP];    // K-chunk of 32 channels, 16 KB

    const int b     = blockIdx.y;
    const int pbase = blockIdx.x * TP;
    const int tid   = threadIdx.x;

    // load W transposed (one-time)
    for (int i = tid; i < CIN*CD; i += 256) {
        int o = i / CIN, c = i % CIN;
        w_s[c*CD + o] = pre_w[i];
    }

    const int to = tid >> 5;   // 0..7  : o-chunk of 8 (uniform within warp)
    const int tp = tid & 31;   // 0..31 : pixel group of 4

    float acc[8][4];
    #pragma unroll
    for (int j = 0; j < 8; j++)
        #pragma unroll
        for (int i = 0; i < 4; i++) acc[j][i] = 0.f;

    const float* xb = x + (size_t)b*CIN*HW + pbase;

    for (int c0 = 0; c0 < CIN; c0 += 32) {
        __syncthreads();
        // load 32 x 128 chunk, 4 float4 per thread
        #pragma unroll
        for (int r = 0; r < 4; r++) {
            int s    = tid + r*256;      // 0..1023 float4 slots
            int row  = s >> 5;           // 0..31
            int col4 = s & 31;           // 0..31
            float4 v = reinterpret_cast<const float4*>(xb + (size_t)(c0+row)*HW)[col4];
            reinterpret_cast<float4*>(x_s)[s] = v;
        }
        __syncthreads();

        #pragma unroll 4
        for (int cc = 0; cc < 32; cc++) {
            float4 xv = *reinterpret_cast<const float4*>(&x_s[cc*TP + tp*4]);
            const float* wrow = &w_s[(c0+cc)*CD + to*8];
            float wf[8];
            #pragma unroll
            for (int j = 0; j < 8; j++) wf[j] = wrow[j];
            #pragma unroll
            for (int j = 0; j < 8; j++) {
                acc[j][0] += wf[j]*xv.x;
                acc[j][1] += wf[j]*xv.y;
                acc[j][2] += wf[j]*xv.z;
                acc[j][3] += wf[j]*xv.w;
            }
        }
    }

    float* yb = g_y + (size_t)b*CD*HW + pbase;
    #pragma unroll
    for (int j = 0; j < 8; j++) {
        int o = to*8 + j;
        float bias = pre_b[o];
        float4 v = make_float4(acc[j][0]+bias, acc[j][1]+bias,
                               acc[j][2]+bias, acc[j][3]+bias);
        *reinterpret_cast<float4*>(&yb[(size_t)o*HW + tp*4]) = v;
    }
}

// ============================================================
// Kernel B: global pooling per (b, channel): max + mean
// ============================================================
__global__ void pool_kernel() {
    const int bo  = blockIdx.x;          // 0..511
    const int tid = threadIdx.x;
    const float* p = g_y + (size_t)bo * HW;
    float mx = -3.4e38f, sm = 0.f;
    for (int i = tid; i < HW; i += 256) {
        float v = p[i];
        mx = fmaxf(mx, v);
        sm += v;
    }
    #pragma unroll
    for (int o = 16; o; o >>= 1) {
        mx = fmaxf(mx, __shfl_xor_sync(0xffffffffu, mx, o));
        sm += __shfl_xor_sync(0xffffffffu, sm, o);
    }
    __shared__ float smx[8], ssm[8];
    if ((tid & 31) == 0) { smx[tid>>5] = mx; ssm[tid>>5] = sm; }
    __syncthreads();
    if (tid == 0) {
        float m = smx[0], s = ssm[0];
        #pragma unroll
        for (int i = 1; i < 8; i++) { m = fmaxf(m, smx[i]); s += ssm[i]; }
        g_pooled[bo] = m + s * (1.0f/(float)HW);
    }
}

// ============================================================
// Kernel C: gate network, top-2 selection, softmax coefficients
// One thread per batch element.
// ============================================================
__global__ void gate_kernel(const float* __restrict__ gw0, const float* __restrict__ gb0,
                            const float* __restrict__ gw1, const float* __restrict__ gb1) {
    int b = threadIdx.x;
    if (b >= BATCH) return;
    const float* pl = g_pooled + b*CD;

    float logits[NE], noise[NE];
    #pragma unroll
    for (int e = 0; e < NE; e++) {
        float a0 = gb0[e], a1 = gb1[e];
        for (int c = 0; c < CD; c++) {
            float pv = pl[c];
            a0 += pv * gw0[e*CD + c];
            a1 += pv * gw1[e*CD + c];
        }
        logits[e] = (a1 > 0.f) ? a1 : 0.2f*a1;                 // leaky_relu 0.2
        noise[e]  = (a0 > 20.f) ? a0 : log1pf(expf(a0));       // softplus
    }
    float mean = 0.f;
    #pragma unroll
    for (int e = 0; e < NE; e++) mean += noise[e];
    mean *= 0.25f;
    float var = 0.f;
    #pragma unroll
    for (int e = 0; e < NE; e++) { float d = noise[e]-mean; var += d*d; }
    float stdv = sqrtf(var * (1.0f/3.0f));                     // ddof=1, n=4
    float scores[NE];
    #pragma unroll
    for (int e = 0; e < NE; e++) scores[e] = logits[e] + (noise[e]-mean)/stdv;

    // top-2 (lowest index wins ties, matching top_k)
    int i1 = 0;
    #pragma unroll
    for (int e = 1; e < NE; e++) if (scores[e] > scores[i1]) i1 = e;
    int i2 = -1;
    #pragma unroll
    for (int e = 0; e < NE; e++) {
        if (e == i1) continue;
        if (i2 < 0 || scores[e] > scores[i2]) i2 = e;
    }
    float m  = fmaxf(logits[i1], logits[i2]);
    float e1 = expf(logits[i1]-m), e2 = expf(logits[i2]-m);
    float inv = 1.0f/(e1+e2);
    #pragma unroll
    for (int e = 0; e < NE; e++) g_cof[b*NE+e] = 0.f;
    g_cof[b*NE+i1] = e1*inv;
    g_cof[b*NE+i2] = e2*inv;
}

// ============================================================
// Kernel D: fused top-2 experts
// dwconv3x3 -> exact GELU -> dwconv3x3, weighted accumulate.
// Block handles one (batch, channel, 16-row tile of 128-wide image).
// NOTE: reference semantics — h = gelu(dwconv1(y)) exists ONLY on the
// valid 128x128 grid; dwconv2 sees ZEROS outside it (SAME padding of h).
// ============================================================
#define TH 16
__global__ void expert_kernel(const float* __restrict__ exp_w1, const float* __restrict__ exp_b1,
                              const float* __restrict__ exp_w2, const float* __restrict__ exp_b2,
                              float* __restrict__ out) {
    __shared__ float ys[(TH+4)*(Ww+4)];   // y tile with halo 2: 20 x 132
    __shared__ float hs[(TH+2)*(Ww+2)];   // gelu(dwconv1) with halo 1: 18 x 130

    const int tile = blockIdx.x;          // 0..7
    const int c    = blockIdx.y;          // 0..63
    const int b    = blockIdx.z;          // 0..7
    const int r0   = tile * TH;
    const int tid  = threadIdx.x;

    // gating coefficients for this batch (uniform across block)
    float cof[NE];
    #pragma unroll
    for (int e = 0; e < NE; e++) cof[e] = g_cof[b*NE + e];

    // load y tile with halo (zero SAME padding)
    const float* yb = g_y + ((size_t)b*CD + c)*HW;
    for (int i = tid; i < (TH+4)*(Ww+4); i += 256) {
        int rr = i / (Ww+4), cc = i % (Ww+4);
        int gr = r0 - 2 + rr, gc = cc - 2;
        float v = 0.f;
        if (gr >= 0 && gr < Hh && gc >= 0 && gc < Ww) v = yb[gr*Ww + gc];
        ys[i] = v;
    }
    __syncthreads();

    float oacc[8];
    #pragma unroll
    for (int k = 0; k < 8; k++) oacc[k] = 0.f;

    for (int e = 0; e < NE; e++) {
        float ce = cof[e];
        if (ce == 0.f) continue;    // uniform branch (same b across block)

        const float* pw1 = exp_w1 + (size_t)(e*CD + c)*9;
        const float* pw2 = exp_w2 + (size_t)(e*CD + c)*9;
        float w1[9], w2[9];
        #pragma unroll
        for (int j = 0; j < 9; j++) { w1[j] = pw1[j]; w2[j] = pw2[j]; }
        const float b1 = exp_b1[e*CD + c];
        const float b2 = exp_b2[e*CD + c];

        // h = gelu(dwconv1(y)) over tile + halo 1  (18 x 130 values)
        // h is ZERO outside the valid 128x128 image (matches SAME padding
        // of h in the second conv of the reference).
        for (int i = tid; i < (TH+2)*(Ww+2); i += 256) {
            int rr = i / (Ww+2), cc = i % (Ww+2);
            int gr = r0 - 1 + rr, gc = cc - 1;     // global coords of this h
            float v = 0.f;
            if (gr >= 0 && gr < Hh && gc >= 0 && gc < Ww) {
                float a = b1;
                #pragma unroll
                for (int dy = 0; dy < 3; dy++)
                    #pragma unroll
                    for (int dx = 0; dx < 3; dx++)
                        a += ys[(rr+dy)*(Ww+4) + (cc+dx)] * w1[dy*3+dx];
                v = a * normcdff(a);   // exact GELU: x * Phi(x)
            }
            hs[i] = v;
        }
        __syncthreads();

        // out += ce * dwconv2(h) over the 16 x 128 tile
        #pragma unroll
        for (int k = 0; k < 8; k++) {
            int i  = tid + k*256;
            int rr = i / Ww, cc = i % Ww;
            float a = b2;
            #pragma unroll
            for (int dy = 0; dy < 3; dy++)
                #pragma unroll
                for (int dx = 0; dx < 3; dx++)
                    a += hs[(rr+dy)*(Ww+2) + (cc+dx)] * w2[dy*3+dx];
            oacc[k] += ce * a;
        }
        __syncthreads();   // hs reused by next expert
    }

    float* ob = out + ((size_t)b*CD + c)*HW + r0*Ww;
    #pragma unroll
    for (int k = 0; k < 8; k++) ob[tid + k*256] = oacc[k];
}

// ============================================================
extern "C" void kernel_launch(void* const* d_in, const int* in_sizes, int n_in,
                              void* d_out, int out_size) {
    const float* x      = (const float*)d_in[0];
    const float* pre_w  = (const float*)d_in[1];
    const float* pre_b  = (const float*)d_in[2];
    const float* gw0    = (const float*)d_in[3];
    const float* gb0    = (const float*)d_in[4];
    const float* gw1    = (const float*)d_in[5];
    const float* gb1    = (const float*)d_in[6];
    const float* ew1    = (const float*)d_in[7];
    const float* eb1    = (const float*)d_in[8];
    const float* ew2    = (const float*)d_in[9];
    const float* eb2    = (const float*)d_in[10];
    float* out = (float*)d_out;

    dim3 gA(HW/TP, BATCH);
    prefuse_kernel<<<gA, 256>>>(x, pre_w, pre_b);
    pool_kernel<<<BATCH*CD, 256>>>();
    gate_kernel<<<1, 32>>>(gw0, gb0, gw1, gb1);
    dim3 gD(Hh/TH, CD, BATCH);
    expert_kernel<<<gD, 256>>>(ew1, eb1, ew2, eb2, out);
}

// round 3
// speedup vs baseline: 1.1767x; 1.1767x over previous
#include <cuda_runtime.h>
#include <math.h>

#define BATCH 8
#define CIN   128
#define CD    64
#define Hh    128
#define Ww    128
#define HW    (Hh*Ww)
#define NE    4

typedef unsigned long long ull;

// ---- scratch (device globals; no allocation allowed) ----
__device__ float g_y[(size_t)BATCH*CD*HW];      // pre_fuse output, 33.5 MB
__device__ float g_pooled[BATCH*CD];            // max + mean pooled
__device__ float g_cof[BATCH*NE];               // gating coefficients (0 for unselected)

// ---- packed fp32x2 helpers (Blackwell FFMA2, PTX-only) ----
__device__ __forceinline__ void ffma2(ull& d, ull a, ull b) {
    asm("fma.rn.f32x2 %0, %1, %2, %0;" : "+l"(d) : "l"(a), "l"(b));
}
__device__ __forceinline__ ull dup2(float v) {
    ull r;
    asm("mov.b64 %0, {%1, %1};" : "=l"(r) : "f"(v));
    return r;
}
__device__ __forceinline__ float2 unpk2(ull v) {
    float2 r;
    asm("mov.b64 {%0, %1}, %2;" : "=f"(r.x), "=f"(r.y) : "l"(v));
    return r;
}

// ============================================================
// Kernel A: pre_fuse 1x1 conv  y[b,o,p] = sum_c x[b,c,p]*W[o,c] + bias[o]
// 256 threads: 8 o-groups (of 8 channels) x 32 pixel-groups (of 4 pixels).
// FFMA2 lanes = 2 consecutive output channels; W pairs load as LDS.64
// from the transposed weight tile, x duplicated via mov.b64.
// ============================================================
#define TP 128
__global__ void prefuse_kernel(const float* __restrict__ x,
                               const float* __restrict__ pre_w,
                               const float* __restrict__ pre_b) {
    __shared__ __align__(16) float w_s[CIN*CD];   // transposed: [c][o], 32 KB
    __shared__ __align__(16) float x_s[32*TP];    // K-chunk of 32 channels, 16 KB

    const int b     = blockIdx.y;
    const int pbase = blockIdx.x * TP;
    const int tid   = threadIdx.x;

    // load W transposed (one-time)
    for (int i = tid; i < CIN*CD; i += 256) {
        int o = i / CIN, c = i % CIN;
        w_s[c*CD + o] = pre_w[i];
    }

    const int to = tid >> 5;   // 0..7  : o-chunk of 8 (uniform within warp)
    const int tp = tid & 31;   // 0..31 : pixel group of 4

    // acc[jp][px]: lanes = channels (to*8+jp*2, to*8+jp*2+1), pixel px
    ull acc[4][4];
    #pragma unroll
    for (int jp = 0; jp < 4; jp++)
        #pragma unroll
        for (int px = 0; px < 4; px++) acc[jp][px] = 0ULL;

    const float* xb = x + (size_t)b*CIN*HW + pbase;

    for (int c0 = 0; c0 < CIN; c0 += 32) {
        __syncthreads();
        // load 32 x 128 chunk, 4 float4 per thread
        #pragma unroll
        for (int r = 0; r < 4; r++) {
            int s    = tid + r*256;      // 0..1023 float4 slots
            int row  = s >> 5;           // 0..31
            int col4 = s & 31;           // 0..31
            float4 v = reinterpret_cast<const float4*>(xb + (size_t)(c0+row)*HW)[col4];
            reinterpret_cast<float4*>(x_s)[s] = v;
        }
        __syncthreads();

        #pragma unroll 8
        for (int cc = 0; cc < 32; cc++) {
            float4 xv = *reinterpret_cast<const float4*>(&x_s[cc*TP + tp*4]);
            ull xd[4];
            xd[0] = dup2(xv.x); xd[1] = dup2(xv.y);
            xd[2] = dup2(xv.z); xd[3] = dup2(xv.w);
            const ull* wrow = reinterpret_cast<const ull*>(&w_s[(c0+cc)*CD + to*8]);
            #pragma unroll
            for (int jp = 0; jp < 4; jp++) {
                ull wd = wrow[jp];
                #pragma unroll
                for (int px = 0; px < 4; px++) ffma2(acc[jp][px], xd[px], wd);
            }
        }
    }

    float* yb = g_y + (size_t)b*CD*HW + pbase;
    #pragma unroll
    for (int jp = 0; jp < 4; jp++) {
        int o = to*8 + jp*2;
        float b0 = pre_b[o], b1 = pre_b[o+1];
        float2 p0 = unpk2(acc[jp][0]);
        float2 p1 = unpk2(acc[jp][1]);
        float2 p2 = unpk2(acc[jp][2]);
        float2 p3 = unpk2(acc[jp][3]);
        float4 v0 = make_float4(p0.x+b0, p1.x+b0, p2.x+b0, p3.x+b0);
        float4 v1 = make_float4(p0.y+b1, p1.y+b1, p2.y+b1, p3.y+b1);
        *reinterpret_cast<float4*>(&yb[(size_t)o*HW     + tp*4]) = v0;
        *reinterpret_cast<float4*>(&yb[(size_t)(o+1)*HW + tp*4]) = v1;
    }
}

// ============================================================
// Kernel B: global pooling per (b, channel): max + mean
// ============================================================
__global__ void pool_kernel() {
    const int bo  = blockIdx.x;          // 0..511
    const int tid = threadIdx.x;
    const float* p = g_y + (size_t)bo * HW;
    float mx = -3.4e38f, sm = 0.f;
    for (int i = tid; i < HW; i += 256) {
        float v = p[i];
        mx = fmaxf(mx, v);
        sm += v;
    }
    #pragma unroll
    for (int o = 16; o; o >>= 1) {
        mx = fmaxf(mx, __shfl_xor_sync(0xffffffffu, mx, o));
        sm += __shfl_xor_sync(0xffffffffu, sm, o);
    }
    __shared__ float smx[8], ssm[8];
    if ((tid & 31) == 0) { smx[tid>>5] = mx; ssm[tid>>5] = sm; }
    __syncthreads();
    if (tid == 0) {
        float m = smx[0], s = ssm[0];
        #pragma unroll
        for (int i = 1; i < 8; i++) { m = fmaxf(m, smx[i]); s += ssm[i]; }
        g_pooled[bo] = m + s * (1.0f/(float)HW);
    }
}

// ============================================================
// Kernel C: gate network, top-2 selection, softmax coefficients
// ============================================================
__global__ void gate_kernel(const float* __restrict__ gw0, const float* __restrict__ gb0,
                            const float* __restrict__ gw1, const float* __restrict__ gb1) {
    int b = threadIdx.x;
    if (b >= BATCH) return;
    const float* pl = g_pooled + b*CD;

    float logits[NE], noise[NE];
    #pragma unroll
    for (int e = 0; e < NE; e++) {
        float a0 = gb0[e], a1 = gb1[e];
        for (int c = 0; c < CD; c++) {
            float pv = pl[c];
            a0 += pv * gw0[e*CD + c];
            a1 += pv * gw1[e*CD + c];
        }
        logits[e] = (a1 > 0.f) ? a1 : 0.2f*a1;                 // leaky_relu 0.2
        noise[e]  = (a0 > 20.f) ? a0 : log1pf(expf(a0));       // softplus
    }
    float mean = 0.f;
    #pragma unroll
    for (int e = 0; e < NE; e++) mean += noise[e];
    mean *= 0.25f;
    float var = 0.f;
    #pragma unroll
    for (int e = 0; e < NE; e++) { float d = noise[e]-mean; var += d*d; }
    float stdv = sqrtf(var * (1.0f/3.0f));                     // ddof=1, n=4
    float scores[NE];
    #pragma unroll
    for (int e = 0; e < NE; e++) scores[e] = logits[e] + (noise[e]-mean)/stdv;

    int i1 = 0;
    #pragma unroll
    for (int e = 1; e < NE; e++) if (scores[e] > scores[i1]) i1 = e;
    int i2 = -1;
    #pragma unroll
    for (int e = 0; e < NE; e++) {
        if (e == i1) continue;
        if (i2 < 0 || scores[e] > scores[i2]) i2 = e;
    }
    float m  = fmaxf(logits[i1], logits[i2]);
    float e1 = expf(logits[i1]-m), e2 = expf(logits[i2]-m);
    float inv = 1.0f/(e1+e2);
    #pragma unroll
    for (int e = 0; e < NE; e++) g_cof[b*NE+e] = 0.f;
    g_cof[b*NE+i1] = e1*inv;
    g_cof[b*NE+i2] = e2*inv;
}

// ============================================================
// Kernel D: fused top-2 experts — column-stationary version.
// Block = 256 threads = 128 columns x 2 row-groups.
// Each thread owns one image column; all row iteration uses register
// sliding windows (3 new LDS per row, no div/mod, immediate smem offsets).
//
// Shared layouts (stride 132 floats):
//   ys[20][132] : y with halo 2.  col index c <-> global col c-2.
//   hs[18][132] : gelu(dwconv1).  col index c <-> global col c-2.
//                 h == 0 outside the valid 128x128 image.
// ============================================================
#define TH 16
#define YS_W 132
__global__ void expert_kernel(const float* __restrict__ exp_w1, const float* __restrict__ exp_b1,
                              const float* __restrict__ exp_w2, const float* __restrict__ exp_b2,
                              float* __restrict__ out) {
    __shared__ float ys[20*YS_W];
    __shared__ float hs[18*YS_W];

    const int tile = blockIdx.x;          // 0..7
    const int c    = blockIdx.y;          // 0..63
    const int b    = blockIdx.z;          // 0..7
    const int r0   = tile * TH;
    const int tid  = threadIdx.x;
    const int tp   = tid & 127;           // column 0..127
    const int rg   = tid >> 7;            // row-group 0/1

    // gating coefficients for this batch (uniform across block)
    float cof[NE];
    #pragma unroll
    for (int e = 0; e < NE; e++) cof[e] = g_cof[b*NE + e];

    // ---- load y tile with halo: rows 0..19 (global r0-2 .. r0+17) ----
    const float* yb = g_y + ((size_t)b*CD + c)*HW;
    #pragma unroll
    for (int k = 0; k < 10; k++) {
        int r  = rg*10 + k;
        int gr = r0 - 2 + r;
        float v = (gr >= 0 && gr < Hh) ? yb[gr*Ww + tp] : 0.f;
        ys[r*YS_W + tp + 2] = v;
        if (tp < 2)    ys[r*YS_W + tp]       = 0.f;   // cols -2,-1
        if (tp >= 126) ys[r*YS_W + tp + 4]   = 0.f;   // cols 128,129
    }
    // zero the hs border columns (global cols -1 and 128) once
    if (tid < 18) {
        hs[tid*YS_W + 1]   = 0.f;
        hs[tid*YS_W + 130] = 0.f;
    }
    __syncthreads();

    float oacc[8];
    #pragma unroll
    for (int k = 0; k < 8; k++) oacc[k] = 0.f;

    for (int e = 0; e < NE; e++) {
        float ce = cof[e];
        if (ce == 0.f) continue;    // uniform branch (same b across block)

        const float* pw1 = exp_w1 + (size_t)(e*CD + c)*9;
        const float* pw2 = exp_w2 + (size_t)(e*CD + c)*9;
        float w1[9], w2[9];
        #pragma unroll
        for (int j = 0; j < 9; j++) { w1[j] = pw1[j]; w2[j] = pw2[j]; }
        const float bb1 = exp_b1[e*CD + c];
        const float bb2 = exp_b2[e*CD + c];

        // ---- conv1 + GELU -> hs, rows rg*9 .. rg*9+8, fixed col tp+2 ----
        {
            const int rs = rg * 9;
            const float* y0 = &ys[rs*YS_W + tp + 1];
            float a0 = y0[0],        a1 = y0[1],        a2 = y0[2];
            float d0 = y0[YS_W],     d1 = y0[YS_W+1],   d2 = y0[YS_W+2];
            #pragma unroll
            for (int k = 0; k < 9; k++) {
                const float* yr = y0 + (k+2)*YS_W;
                float f0 = yr[0], f1 = yr[1], f2 = yr[2];
                float a = bb1;
                a += a0*w1[0] + a1*w1[1] + a2*w1[2];
                a += d0*w1[3] + d1*w1[4] + d2*w1[5];
                a += f0*w1[6] + f1*w1[7] + f2*w1[8];
                int gr = r0 - 1 + rs + k;
                float hval = (gr >= 0 && gr < Hh) ? a * normcdff(a) : 0.f;
                hs[(rs+k)*YS_W + tp + 2] = hval;
                a0 = d0; a1 = d1; a2 = d2;
                d0 = f0; d1 = f1; d2 = f2;
            }
        }
        __syncthreads();

        // ---- conv2 -> oacc, rows rg*8 .. rg*8+7, fixed col tp ----
        {
            const int rs = rg * 8;
            const float* h0 = &hs[rs*YS_W + tp + 1];
            float a0 = h0[0],        a1 = h0[1],        a2 = h0[2];
            float d0 = h0[YS_W],     d1 = h0[YS_W+1],   d2 = h0[YS_W+2];
            #pragma unroll
            for (int k = 0; k < 8; k++) {
                const float* hr = h0 + (k+2)*YS_W;
                float f0 = hr[0], f1 = hr[1], f2 = hr[2];
                float a = bb2;
                a += a0*w2[0] + a1*w2[1] + a2*w2[2];
                a += d0*w2[3] + d1*w2[4] + d2*w2[5];
                a += f0*w2[6] + f1*w2[7] + f2*w2[8];
                oacc[k] += ce * a;
                a0 = d0; a1 = d1; a2 = d2;
                d0 = f0; d1 = f1; d2 = f2;
            }
        }
        __syncthreads();   // hs reused by next expert
    }

    float* ob = out + ((size_t)b*CD + c)*HW + (r0 + rg*8)*Ww + tp;
    #pragma unroll
    for (int k = 0; k < 8; k++) ob[k*Ww] = oacc[k];
}

// ============================================================
extern "C" void kernel_launch(void* const* d_in, const int* in_sizes, int n_in,
                              void* d_out, int out_size) {
    const float* x      = (const float*)d_in[0];
    const float* pre_w  = (const float*)d_in[1];
    const float* pre_b  = (const float*)d_in[2];
    const float* gw0    = (const float*)d_in[3];
    const float* gb0    = (const float*)d_in[4];
    const float* gw1    = (const float*)d_in[5];
    const float* gb1    = (const float*)d_in[6];
    const float* ew1    = (const float*)d_in[7];
    const float* eb1    = (const float*)d_in[8];
    const float* ew2    = (const float*)d_in[9];
    const float* eb2    = (const float*)d_in[10];
    float* out = (float*)d_out;

    dim3 gA(HW/TP, BATCH);
    prefuse_kernel<<<gA, 256>>>(x, pre_w, pre_b);
    pool_kernel<<<BATCH*CD, 256>>>();
    gate_kernel<<<1, 32>>>(gw0, gb0, gw1, gb1);
    dim3 gD(Hh/TH, CD, BATCH);
    expert_kernel<<<gD, 256>>>(ew1, eb1, ew2, eb2, out);
}